// round 1
// baseline (speedup 1.0000x reference)
#include <cuda_runtime.h>
#include <cstddef>

#define HN  8
#define DM  512
#define DKH 64
#define BB  8
#define SS  1024
#define MR  (BB * SS)                      // 8192 rows
#define SL  ((size_t)MR * DM)              // 4,194,304 floats per [8192,512] buffer
#define SCL ((size_t)BB * HN * SS * SS)    // 67,108,864 floats per score buffer

// Scratch: 8 x [8192,512] (qr,kr,vr,qf,kf,vf,or,of) + 2 x [64,1024,1024] scores
__device__ float g_scratch[8 * (size_t)MR * DM + 2 * (size_t)BB * HN * SS * SS];

// ----------------------------------------------------------------------------
// Generic NT SGEMM: C = alpha * A(MxK) * B(NxK)^T (+ bias), z-batched for
// per-(b,h) attention GEMMs. Tiles: 128x128x16, 256 threads, 8x8 per thread.
// All dims are exact multiples of the tiles for this problem; no bounds checks.
// ----------------------------------------------------------------------------
__global__ void __launch_bounds__(256) sgemm_nt(
    const float* __restrict__ A, const float* __restrict__ B,
    float* __restrict__ C, const float* __restrict__ bias,
    int lda, int ldb, int ldc, int K, float alpha,
    size_t sAb, int sAh, size_t sBb, int sBh, size_t sCz)
{
    const int z  = blockIdx.z;
    const int zb = z >> 3, zh = z & 7;
    A += (size_t)zb * sAb + (size_t)zh * sAh;
    B += (size_t)zb * sBb + (size_t)zh * sBh;
    C += (size_t)z * sCz;

    __shared__ float As[16][128];
    __shared__ float Bs[16][128];

    const int tid = threadIdx.x;
    const int m0 = blockIdx.y * 128;
    const int n0 = blockIdx.x * 128;

    const int ldRow = tid >> 2;          // 0..63 (two row-groups: +0, +64)
    const int ldCol = (tid & 3) << 2;    // 0,4,8,12

    const int rowBase = (tid >> 4) << 2; // 0..60
    const int colBase = (tid & 15) << 2; // 0..60

    float acc[8][8];
#pragma unroll
    for (int i = 0; i < 8; i++)
#pragma unroll
        for (int j = 0; j < 8; j++) acc[i][j] = 0.f;

    for (int k0 = 0; k0 < K; k0 += 16) {
#pragma unroll
        for (int g = 0; g < 2; g++) {
            const int r = ldRow + g * 64;
            float4 va = *(const float4*)(A + (size_t)(m0 + r) * lda + k0 + ldCol);
            As[ldCol + 0][r] = va.x; As[ldCol + 1][r] = va.y;
            As[ldCol + 2][r] = va.z; As[ldCol + 3][r] = va.w;
            float4 vb = *(const float4*)(B + (size_t)(n0 + r) * ldb + k0 + ldCol);
            Bs[ldCol + 0][r] = vb.x; Bs[ldCol + 1][r] = vb.y;
            Bs[ldCol + 2][r] = vb.z; Bs[ldCol + 3][r] = vb.w;
        }
        __syncthreads();
#pragma unroll
        for (int kk = 0; kk < 16; kk++) {
            float a[8], b[8];
            *(float4*)&a[0] = *(const float4*)&As[kk][rowBase];
            *(float4*)&a[4] = *(const float4*)&As[kk][rowBase + 64];
            *(float4*)&b[0] = *(const float4*)&Bs[kk][colBase];
            *(float4*)&b[4] = *(const float4*)&Bs[kk][colBase + 64];
#pragma unroll
            for (int i = 0; i < 8; i++)
#pragma unroll
                for (int j = 0; j < 8; j++)
                    acc[i][j] += a[i] * b[j];
        }
        __syncthreads();
    }

#pragma unroll
    for (int gi = 0; gi < 2; gi++)
#pragma unroll
        for (int i = 0; i < 4; i++) {
            const int rr = m0 + gi * 64 + rowBase + i;
#pragma unroll
            for (int gj = 0; gj < 2; gj++) {
                const int cc = n0 + gj * 64 + colBase;
                const float* ap = &acc[gi * 4 + i][gj * 4];
                float4 o;
                if (bias) {
                    o.x = alpha * ap[0] + bias[cc + 0];
                    o.y = alpha * ap[1] + bias[cc + 1];
                    o.z = alpha * ap[2] + bias[cc + 2];
                    o.w = alpha * ap[3] + bias[cc + 3];
                } else {
                    o.x = alpha * ap[0]; o.y = alpha * ap[1];
                    o.z = alpha * ap[2]; o.w = alpha * ap[3];
                }
                *(float4*)(C + (size_t)rr * ldc + cc) = o;
            }
        }
}

// ----------------------------------------------------------------------------
// Per-row softmax of both streams + elementwise max merge. One block per row
// (256 threads x 4 elems = 1024). Writes merged P in-place into sR.
// ----------------------------------------------------------------------------
__global__ void __launch_bounds__(256) softmax_merge(
    const float* __restrict__ sR, const float* __restrict__ sF,
    float* __restrict__ P)
{
    const size_t row = blockIdx.x;
    const int t = threadIdx.x;
    const int lane = t & 31, warp = t >> 5;

    const float4 a = ((const float4*)(sR + row * SS))[t];
    const float4 b = ((const float4*)(sF + row * SS))[t];

    __shared__ float red[8];

    auto reduce_max = [&](float v) -> float {
#pragma unroll
        for (int o = 16; o; o >>= 1) v = fmaxf(v, __shfl_xor_sync(0xffffffffu, v, o));
        if (lane == 0) red[warp] = v;
        __syncthreads();
        float m = red[0];
#pragma unroll
        for (int i = 1; i < 8; i++) m = fmaxf(m, red[i]);
        __syncthreads();
        return m;
    };
    auto reduce_sum = [&](float v) -> float {
#pragma unroll
        for (int o = 16; o; o >>= 1) v += __shfl_xor_sync(0xffffffffu, v, o);
        if (lane == 0) red[warp] = v;
        __syncthreads();
        float s = 0.f;
#pragma unroll
        for (int i = 0; i < 8; i++) s += red[i];
        __syncthreads();
        return s;
    };

    const float Mr = reduce_max(fmaxf(fmaxf(a.x, a.y), fmaxf(a.z, a.w)));
    const float Mf = reduce_max(fmaxf(fmaxf(b.x, b.y), fmaxf(b.z, b.w)));

    float4 er, ef;
    er.x = __expf(a.x - Mr); er.y = __expf(a.y - Mr);
    er.z = __expf(a.z - Mr); er.w = __expf(a.w - Mr);
    ef.x = __expf(b.x - Mf); ef.y = __expf(b.y - Mf);
    ef.z = __expf(b.z - Mf); ef.w = __expf(b.w - Mf);

    const float Dr = reduce_sum(er.x + er.y + er.z + er.w);
    const float Df = reduce_sum(ef.x + ef.y + ef.z + ef.w);
    const float ir = 1.f / Dr, iff = 1.f / Df;

    float4 o;
    o.x = fmaxf(er.x * ir, ef.x * iff);
    o.y = fmaxf(er.y * ir, ef.y * iff);
    o.z = fmaxf(er.z * ir, ef.z * iff);
    o.w = fmaxf(er.w * ir, ef.w * iff);
    ((float4*)(P + row * SS))[t] = o;
}

// ----------------------------------------------------------------------------
// Fused dual-stream PV: O_r = P @ V_r, O_f = P @ V_f per (b,h).
// Tiles: 128(q) x 64(d) x 16(k), 256 threads, 8x4 per thread per stream.
// Reads merged P once for both streams.
// ----------------------------------------------------------------------------
__global__ void __launch_bounds__(256) attn_pv(
    const float* __restrict__ P, const float* __restrict__ Vr,
    const float* __restrict__ Vf, float* __restrict__ Or,
    float* __restrict__ Of)
{
    const int z = blockIdx.y, zb = z >> 3, zh = z & 7;
    const int m0 = blockIdx.x * 128;
    const float* Pz = P + (size_t)z * SS * SS;
    const size_t voff = (size_t)zb * SS * DM + (size_t)zh * DKH;
    const float* vr = Vr + voff;
    const float* vf = Vf + voff;

    __shared__ float Ps[16][128];
    __shared__ float Vs[2][16][64];

    const int tid = threadIdx.x;
    const int pRow = tid >> 2, pCol = (tid & 3) << 2;
    const int vRow = tid >> 4, vCol = (tid & 15) << 2;
    const int rowBase = (tid >> 4) << 2;
    const int colBase = (tid & 15) << 2;

    float accR[8][4], accF[8][4];
#pragma unroll
    for (int i = 0; i < 8; i++)
#pragma unroll
        for (int j = 0; j < 4; j++) { accR[i][j] = 0.f; accF[i][j] = 0.f; }

    for (int k0 = 0; k0 < SS; k0 += 16) {
#pragma unroll
        for (int g = 0; g < 2; g++) {
            const int r = pRow + g * 64;
            float4 v = *(const float4*)(Pz + (size_t)(m0 + r) * SS + k0 + pCol);
            Ps[pCol + 0][r] = v.x; Ps[pCol + 1][r] = v.y;
            Ps[pCol + 2][r] = v.z; Ps[pCol + 3][r] = v.w;
        }
        {
            float4 v0 = *(const float4*)(vr + (size_t)(k0 + vRow) * DM + vCol);
            *(float4*)&Vs[0][vRow][vCol] = v0;
            float4 v1 = *(const float4*)(vf + (size_t)(k0 + vRow) * DM + vCol);
            *(float4*)&Vs[1][vRow][vCol] = v1;
        }
        __syncthreads();
#pragma unroll
        for (int kk = 0; kk < 16; kk++) {
            float a[8];
            *(float4*)&a[0] = *(const float4*)&Ps[kk][rowBase];
            *(float4*)&a[4] = *(const float4*)&Ps[kk][rowBase + 64];
            const float4 br = *(const float4*)&Vs[0][kk][colBase];
            const float4 bf = *(const float4*)&Vs[1][kk][colBase];
#pragma unroll
            for (int i = 0; i < 8; i++) {
                accR[i][0] += a[i] * br.x; accR[i][1] += a[i] * br.y;
                accR[i][2] += a[i] * br.z; accR[i][3] += a[i] * br.w;
                accF[i][0] += a[i] * bf.x; accF[i][1] += a[i] * bf.y;
                accF[i][2] += a[i] * bf.z; accF[i][3] += a[i] * bf.w;
            }
        }
        __syncthreads();
    }

    float* orp = Or + voff;
    float* ofp = Of + voff;
#pragma unroll
    for (int gi = 0; gi < 2; gi++)
#pragma unroll
        for (int i = 0; i < 4; i++) {
            const int rr = m0 + gi * 64 + rowBase + i;
            const int ai = gi * 4 + i;
            *(float4*)(orp + (size_t)rr * DM + colBase) =
                make_float4(accR[ai][0], accR[ai][1], accR[ai][2], accR[ai][3]);
            *(float4*)(ofp + (size_t)rr * DM + colBase) =
                make_float4(accF[ai][0], accF[ai][1], accF[ai][2], accF[ai][3]);
        }
}

// ----------------------------------------------------------------------------
extern "C" void kernel_launch(void* const* d_in, const int* in_sizes, int n_in,
                              void* d_out, int out_size)
{
    const float* rgb  = (const float*)d_in[0];
    const float* flow = (const float*)d_in[1];
    const float* Wq1 = (const float*)d_in[2];  const float* bq1 = (const float*)d_in[3];
    const float* Wk1 = (const float*)d_in[4];  const float* bk1 = (const float*)d_in[5];
    const float* Wv1 = (const float*)d_in[6];  const float* bv1 = (const float*)d_in[7];
    const float* Wq2 = (const float*)d_in[8];  const float* bq2 = (const float*)d_in[9];
    const float* Wk2 = (const float*)d_in[10]; const float* bk2 = (const float*)d_in[11];
    const float* Wv2 = (const float*)d_in[12]; const float* bv2 = (const float*)d_in[13];
    const float* Wo1 = (const float*)d_in[14]; const float* bo1 = (const float*)d_in[15];
    const float* Wo2 = (const float*)d_in[16]; const float* bo2 = (const float*)d_in[17];

    float* base = nullptr;
    cudaGetSymbolAddress((void**)&base, g_scratch);

    float* qr  = base + 0 * SL;
    float* kr  = base + 1 * SL;
    float* vrr = base + 2 * SL;
    float* qf  = base + 3 * SL;
    float* kf  = base + 4 * SL;
    float* vff = base + 5 * SL;
    float* orr = base + 6 * SL;
    float* off = base + 7 * SL;
    float* sR  = base + 8 * SL;
    float* sF  = sR + SCL;

    const dim3 blk(256);
    const dim3 gProj(4, 64, 1);   // N=512/128, M=8192/128

    // QKV projections (fp32 NT GEMM + bias)
    sgemm_nt<<<gProj, blk>>>(rgb,  Wq1, qr,  bq1, DM, DM, DM, DM, 1.f, 0, 0, 0, 0, 0);
    sgemm_nt<<<gProj, blk>>>(rgb,  Wk1, kr,  bk1, DM, DM, DM, DM, 1.f, 0, 0, 0, 0, 0);
    sgemm_nt<<<gProj, blk>>>(rgb,  Wv1, vrr, bv1, DM, DM, DM, DM, 1.f, 0, 0, 0, 0, 0);
    sgemm_nt<<<gProj, blk>>>(flow, Wq2, qf,  bq2, DM, DM, DM, DM, 1.f, 0, 0, 0, 0, 0);
    sgemm_nt<<<gProj, blk>>>(flow, Wk2, kf,  bk2, DM, DM, DM, DM, 1.f, 0, 0, 0, 0, 0);
    sgemm_nt<<<gProj, blk>>>(flow, Wv2, vff, bv2, DM, DM, DM, DM, 1.f, 0, 0, 0, 0, 0);

    // Scores: S = (Q K^T) / 8 per (b,h), both streams
    const dim3 gSc(8, 8, BB * HN);
    const float scale = 0.125f;
    sgemm_nt<<<gSc, blk>>>(qr, kr, sR, nullptr, DM, DM, SS, DKH, scale,
                           (size_t)SS * DM, DKH, (size_t)SS * DM, DKH, (size_t)SS * SS);
    sgemm_nt<<<gSc, blk>>>(qf, kf, sF, nullptr, DM, DM, SS, DKH, scale,
                           (size_t)SS * DM, DKH, (size_t)SS * DM, DKH, (size_t)SS * SS);

    // Softmax both streams + elementwise-max merge (in-place into sR)
    softmax_merge<<<BB * HN * SS, 256>>>(sR, sF, sR);

    // Dual-stream PV
    attn_pv<<<dim3(8, BB * HN), blk>>>(sR, vrr, vff, orr, off);

    // Output projections straight into d_out (rgb first, flow second)
    float* out = (float*)d_out;
    sgemm_nt<<<gProj, blk>>>(orr, Wo1, out,      bo1, DM, DM, DM, DM, 1.f, 0, 0, 0, 0, 0);
    sgemm_nt<<<gProj, blk>>>(off, Wo2, out + SL, bo2, DM, DM, DM, DM, 1.f, 0, 0, 0, 0, 0);
}

// round 5
// speedup vs baseline: 1.7420x; 1.7420x over previous
#include <cuda_runtime.h>
#include <cuda_bf16.h>
#include <cstdint>
#include <cstddef>

#define HN  8
#define DM  512
#define DKH 64
#define BB  8
#define SS  1024
#define MR  (BB * SS)                      // 8192 rows
#define SL  ((size_t)MR * DM)
#define SCL ((size_t)BB * HN * SS * SS)

// 6 qkv + 2 attn-out + 2 Vt + 2 score buffers
__device__ float g_scratch[10 * SL + 2 * SCL];

// ---------------------------------------------------------------------------
__device__ __forceinline__ uint32_t smem_u32(const void* p) {
    uint32_t a;
    asm("{ .reg .u64 t; cvta.to.shared.u64 t, %1; cvt.u32.u64 %0, t; }" : "=r"(a) : "l"(p));
    return a;
}

__device__ __forceinline__ void ldmx4(uint32_t* r, uint32_t a) {
    asm volatile("ldmatrix.sync.aligned.m8n8.x4.shared.b16 {%0,%1,%2,%3}, [%4];"
                 : "=r"(r[0]), "=r"(r[1]), "=r"(r[2]), "=r"(r[3]) : "r"(a));
}

__device__ __forceinline__ void mma16816(float* c, const uint32_t* a,
                                         uint32_t b0, uint32_t b1) {
    asm volatile(
        "mma.sync.aligned.m16n8k16.row.col.f32.bf16.bf16.f32 "
        "{%0,%1,%2,%3}, {%4,%5,%6,%7}, {%8,%9}, {%0,%1,%2,%3};"
        : "+f"(c[0]), "+f"(c[1]), "+f"(c[2]), "+f"(c[3])
        : "r"(a[0]), "r"(a[1]), "r"(a[2]), "r"(a[3]), "r"(b0), "r"(b1));
}

__device__ __forceinline__ uint32_t pkbf2(float x, float y) {
    __nv_bfloat162 t;
    t.x = __float2bfloat16_rn(x);
    t.y = __float2bfloat16_rn(y);
    return *reinterpret_cast<uint32_t*>(&t);
}

// split fp32x4 -> bf16 hi x4 (uint2) + bf16 lo x4 (uint2)
__device__ __forceinline__ void split4(float4 v, uint2& hi, uint2& lo) {
    __nv_bfloat16 hx = __float2bfloat16_rn(v.x);
    __nv_bfloat16 hy = __float2bfloat16_rn(v.y);
    __nv_bfloat16 hz = __float2bfloat16_rn(v.z);
    __nv_bfloat16 hw = __float2bfloat16_rn(v.w);
    float rx = v.x - __bfloat162float(hx);
    float ry = v.y - __bfloat162float(hy);
    float rz = v.z - __bfloat162float(hz);
    float rw = v.w - __bfloat162float(hw);
    __nv_bfloat162 h01; h01.x = hx; h01.y = hy;
    __nv_bfloat162 h23; h23.x = hz; h23.y = hw;
    hi.x = *reinterpret_cast<uint32_t*>(&h01);
    hi.y = *reinterpret_cast<uint32_t*>(&h23);
    lo.x = pkbf2(rx, ry);
    lo.y = pkbf2(rz, rw);
}

// ---------------------------------------------------------------------------
// HMMA split-bf16 NT GEMM: C = alpha * A(Mx K) * B(128 x K)^T (+bias)
// CTA tile 128x128, K staged 32 floats at a time, double-buffered SMEM.
// 8 warps (2 along M x 4 along N), warp tile 64x32, mma.m16n8k16 bf16.
// DUAL: B rows 0-63 from B (V_r^T), 64-127 from B2 (V_f^T); epilogue routes
// cols <64 -> C, >=64 -> C2 (col-64). Batched via blockIdx.z (zb/zh strides).
// Stage SMEM: A_hi(8K) A_lo(8K) B_hi(8K) B_lo(8K) = 32KB; x2 stages = 64KB.
// ---------------------------------------------------------------------------
template <bool DUAL>
__global__ void __launch_bounds__(256, 1) mma_gemm(
    const float* __restrict__ A, const float* __restrict__ B, const float* __restrict__ B2,
    float* __restrict__ C, float* __restrict__ C2, const float* __restrict__ bias,
    int lda, int ldb, int ldc, int K, float alpha,
    size_t sAb, int sAh, size_t sBb, int sBh, size_t sCb, int sCh)
{
    extern __shared__ char sm[];
    const uint32_t sb = smem_u32(sm);

    const int tid = threadIdx.x, lane = tid & 31, warp = tid >> 5;
    const int z = blockIdx.z, zb = z >> 3, zh = z & 7;
    const int m0 = blockIdx.y * 128, n0 = blockIdx.x * 128;

    A += (size_t)zb * sAb + (size_t)zh * sAh;
    B += (size_t)zb * sBb + (size_t)zh * sBh;
    C += (size_t)zb * sCb + (size_t)zh * sCh;
    if (DUAL) {
        B2 += (size_t)zb * sBb + (size_t)zh * sBh;
        C2 += (size_t)zb * sCb + (size_t)zh * sCh;
    }

    // ---- per-lane compute-side invariants ----
    const int wm = warp & 1, wn = warp >> 1;       // 2 x 4 warp grid
    const int cHi = lane >> 4;                     // A ldmatrix chunk select
    uint32_t rowAoff[4]; int rA3[4];
#pragma unroll
    for (int mb = 0; mb < 4; mb++) {
        const int rowA = wm * 64 + mb * 16 + (lane & 15);
        rowAoff[mb] = rowA * 64;
        rA3[mb] = rowA & 3;
    }
    uint32_t addrBo[4];
#pragma unroll
    for (int nb = 0; nb < 4; nb++) {
        const int rowB = wn * 32 + nb * 8 + (lane & 7);
        const int chB = lane >> 3;
        addrBo[nb] = rowB * 64 + ((uint32_t)(chB ^ (rowB & 3)) << 4);
    }

    float acc[4][4][4];
#pragma unroll
    for (int mb = 0; mb < 4; mb++)
#pragma unroll
        for (int nb = 0; nb < 4; nb++)
#pragma unroll
            for (int r = 0; r < 4; r++) acc[mb][nb][r] = 0.f;

    // ---- loaders ----
    float4 ga[4], gb[4];
    auto ldg_stage = [&](int k0) {
#pragma unroll
        for (int j = 0; j < 4; j++) {
            const int l = tid + 256 * j;
            const int row = l >> 3, c4 = l & 7;
            ga[j] = *(const float4*)(A + (size_t)(m0 + row) * lda + k0 + c4 * 4);
            const float* bp;
            if (DUAL)
                bp = (row < 64) ? (B + (size_t)(n0 + row) * ldb)
                                : (B2 + (size_t)(n0 + row - 64) * ldb);
            else
                bp = B + (size_t)(n0 + row) * ldb;
            gb[j] = *(const float4*)(bp + k0 + c4 * 4);
        }
    };
    auto sts_stage = [&](int buf) {
        char* st = sm + buf * 32768;
#pragma unroll
        for (int j = 0; j < 4; j++) {
            const int l = tid + 256 * j;
            const int row = l >> 3, c4 = l & 7;
            const uint32_t off = row * 64 + ((uint32_t)(((c4 >> 1) ^ (row & 3))) << 4)
                                 + (c4 & 1) * 8;
            uint2 hi, lo;
            split4(ga[j], hi, lo);
            *(uint2*)(st + off) = hi;
            *(uint2*)(st + 8192 + off) = lo;
            split4(gb[j], hi, lo);
            *(uint2*)(st + 16384 + off) = hi;
            *(uint2*)(st + 24576 + off) = lo;
        }
    };

    ldg_stage(0);
    sts_stage(0);
    __syncthreads();

    const int NSTG = K >> 5;
    for (int s = 0; s < NSTG; s++) {
        const int cur = s & 1;
        if (s + 1 < NSTG) ldg_stage((s + 1) << 5);

        const uint32_t stb = sb + cur * 32768;

        uint32_t BH[4][4], BL[4][4];
#pragma unroll
        for (int nb = 0; nb < 4; nb++) {
            const uint32_t a = stb + 16384 + addrBo[nb];
            ldmx4(BH[nb], a);
            ldmx4(BL[nb], a + 8192);
        }
#pragma unroll
        for (int kk = 0; kk < 2; kk++) {
            uint32_t AH[4][4], AL[4][4];
#pragma unroll
            for (int mb = 0; mb < 4; mb++) {
                const uint32_t a = stb + rowAoff[mb]
                                   + ((uint32_t)((2 * kk + cHi) ^ rA3[mb]) << 4);
                ldmx4(AH[mb], a);
                ldmx4(AL[mb], a + 8192);
            }
#pragma unroll
            for (int mb = 0; mb < 4; mb++)
#pragma unroll
                for (int nb = 0; nb < 4; nb++) {
                    mma16816(acc[mb][nb], AH[mb], BH[nb][2 * kk], BH[nb][2 * kk + 1]);
                    mma16816(acc[mb][nb], AH[mb], BL[nb][2 * kk], BL[nb][2 * kk + 1]);
                    mma16816(acc[mb][nb], AL[mb], BH[nb][2 * kk], BH[nb][2 * kk + 1]);
                }
        }

        if (s + 1 < NSTG) sts_stage((s + 1) & 1);
        __syncthreads();
    }

    // ---- epilogue ----
    const int gr = lane >> 2, gc2 = (lane & 3) * 2;
#pragma unroll
    for (int mb = 0; mb < 4; mb++) {
        const int row = m0 + wm * 64 + mb * 16 + gr;
#pragma unroll
        for (int nb = 0; nb < 4; nb++) {
            const int col = wn * 32 + nb * 8 + gc2;
            float* cp;
            int gcol;
            if (DUAL && col >= 64) { cp = C2; gcol = col - 64; }
            else                   { cp = C;  gcol = n0 + col; }
            float2 w0, w1;
            w0.x = alpha * acc[mb][nb][0];
            w0.y = alpha * acc[mb][nb][1];
            w1.x = alpha * acc[mb][nb][2];
            w1.y = alpha * acc[mb][nb][3];
            if (bias) {
                const float bx = bias[gcol], by = bias[gcol + 1];
                w0.x += bx; w0.y += by;
                w1.x += bx; w1.y += by;
            }
            *(float2*)(cp + (size_t)row * ldc + gcol) = w0;
            *(float2*)(cp + (size_t)(row + 8) * ldc + gcol) = w1;
        }
    }
}

// ---------------------------------------------------------------------------
// Per-row dual softmax + elementwise-max merge
// ---------------------------------------------------------------------------
__global__ void __launch_bounds__(256) softmax_merge(
    const float* __restrict__ sR, const float* __restrict__ sF, float* __restrict__ P)
{
    const size_t row = blockIdx.x;
    const int t = threadIdx.x;
    const int lane = t & 31, warp = t >> 5;

    const float4 a = ((const float4*)(sR + row * SS))[t];
    const float4 b = ((const float4*)(sF + row * SS))[t];

    __shared__ float red[8];

    auto reduce_max = [&](float v) -> float {
#pragma unroll
        for (int o = 16; o; o >>= 1) v = fmaxf(v, __shfl_xor_sync(0xffffffffu, v, o));
        if (lane == 0) red[warp] = v;
        __syncthreads();
        float m = red[0];
#pragma unroll
        for (int i = 1; i < 8; i++) m = fmaxf(m, red[i]);
        __syncthreads();
        return m;
    };
    auto reduce_sum = [&](float v) -> float {
#pragma unroll
        for (int o = 16; o; o >>= 1) v += __shfl_xor_sync(0xffffffffu, v, o);
        if (lane == 0) red[warp] = v;
        __syncthreads();
        float s = 0.f;
#pragma unroll
        for (int i = 0; i < 8; i++) s += red[i];
        __syncthreads();
        return s;
    };

    const float Mr = reduce_max(fmaxf(fmaxf(a.x, a.y), fmaxf(a.z, a.w)));
    const float Mf = reduce_max(fmaxf(fmaxf(b.x, b.y), fmaxf(b.z, b.w)));

    float4 er, ef;
    er.x = __expf(a.x - Mr); er.y = __expf(a.y - Mr);
    er.z = __expf(a.z - Mr); er.w = __expf(a.w - Mr);
    ef.x = __expf(b.x - Mf); ef.y = __expf(b.y - Mf);
    ef.z = __expf(b.z - Mf); ef.w = __expf(b.w - Mf);

    const float Dr = reduce_sum(er.x + er.y + er.z + er.w);
    const float Df = reduce_sum(ef.x + ef.y + ef.z + ef.w);
    const float ir = 1.f / Dr, iff = 1.f / Df;

    float4 o;
    o.x = fmaxf(er.x * ir, ef.x * iff);
    o.y = fmaxf(er.y * ir, ef.y * iff);
    o.z = fmaxf(er.z * ir, ef.z * iff);
    o.w = fmaxf(er.w * ir, ef.w * iff);
    ((float4*)(P + row * SS))[t] = o;
}

// ---------------------------------------------------------------------------
// Per-head V transpose: Vt[z][d][s] = V[(zb*S + s)*DM + zh*64 + d]
// ---------------------------------------------------------------------------
__global__ void __launch_bounds__(256) transpose_v(
    const float* __restrict__ V, float* __restrict__ Vt)
{
    __shared__ float t[32][33];
    const int z = blockIdx.z, zbv = z >> 3, zhv = z & 7;
    const int s0 = blockIdx.x * 32, d0 = blockIdx.y * 32;
    const float* Vb = V + (size_t)zbv * SS * DM + zhv * 64;
    for (int i = threadIdx.y; i < 32; i += 8)
        t[i][threadIdx.x] = Vb[(size_t)(s0 + i) * DM + d0 + threadIdx.x];
    __syncthreads();
    float* Vtb = Vt + (size_t)z * DKH * SS;
    for (int i = threadIdx.y; i < 32; i += 8)
        Vtb[(size_t)(d0 + i) * SS + s0 + threadIdx.x] = t[threadIdx.x][i];
}

// ---------------------------------------------------------------------------
extern "C" void kernel_launch(void* const* d_in, const int* in_sizes, int n_in,
                              void* d_out, int out_size)
{
    const float* rgb  = (const float*)d_in[0];
    const float* flow = (const float*)d_in[1];
    const float* Wq1 = (const float*)d_in[2];  const float* bq1 = (const float*)d_in[3];
    const float* Wk1 = (const float*)d_in[4];  const float* bk1 = (const float*)d_in[5];
    const float* Wv1 = (const float*)d_in[6];  const float* bv1 = (const float*)d_in[7];
    const float* Wq2 = (const float*)d_in[8];  const float* bq2 = (const float*)d_in[9];
    const float* Wk2 = (const float*)d_in[10]; const float* bk2 = (const float*)d_in[11];
    const float* Wv2 = (const float*)d_in[12]; const float* bv2 = (const float*)d_in[13];
    const float* Wo1 = (const float*)d_in[14]; const float* bo1 = (const float*)d_in[15];
    const float* Wo2 = (const float*)d_in[16]; const float* bo2 = (const float*)d_in[17];

    float* base = nullptr;
    cudaGetSymbolAddress((void**)&base, g_scratch);

    float* qr  = base + 0 * SL;
    float* kr  = base + 1 * SL;
    float* vrr = base + 2 * SL;
    float* qf  = base + 3 * SL;
    float* kf  = base + 4 * SL;
    float* vff = base + 5 * SL;
    float* orr = base + 6 * SL;
    float* off = base + 7 * SL;
    float* vtR = base + 8 * SL;
    float* vtF = base + 9 * SL;
    float* sR  = base + 10 * SL;
    float* sF  = sR + SCL;

    const int SMEMSZ = 65536;
    static bool attr_set = false;
    cudaFuncSetAttribute((const void*)mma_gemm<false>,
                         cudaFuncAttributeMaxDynamicSharedMemorySize, SMEMSZ);
    cudaFuncSetAttribute((const void*)mma_gemm<true>,
                         cudaFuncAttributeMaxDynamicSharedMemorySize, SMEMSZ);
    (void)attr_set;

    const dim3 blk(256);
    const dim3 gProj(4, 64, 1);

    // QKV projections: C = A @ W^T + b
    mma_gemm<false><<<gProj, blk, SMEMSZ>>>(rgb,  Wq1, nullptr, qr,  nullptr, bq1,
        DM, DM, DM, DM, 1.f, 0, 0, 0, 0, 0, 0);
    mma_gemm<false><<<gProj, blk, SMEMSZ>>>(rgb,  Wk1, nullptr, kr,  nullptr, bk1,
        DM, DM, DM, DM, 1.f, 0, 0, 0, 0, 0, 0);
    mma_gemm<false><<<gProj, blk, SMEMSZ>>>(rgb,  Wv1, nullptr, vrr, nullptr, bv1,
        DM, DM, DM, DM, 1.f, 0, 0, 0, 0, 0, 0);
    mma_gemm<false><<<gProj, blk, SMEMSZ>>>(flow, Wq2, nullptr, qf,  nullptr, bq2,
        DM, DM, DM, DM, 1.f, 0, 0, 0, 0, 0, 0);
    mma_gemm<false><<<gProj, blk, SMEMSZ>>>(flow, Wk2, nullptr, kf,  nullptr, bk2,
        DM, DM, DM, DM, 1.f, 0, 0, 0, 0, 0, 0);
    mma_gemm<false><<<gProj, blk, SMEMSZ>>>(flow, Wv2, nullptr, vff, nullptr, bv2,
        DM, DM, DM, DM, 1.f, 0, 0, 0, 0, 0, 0);

    // V transposes for PV (K-major B operand)
    transpose_v<<<dim3(32, 2, 64), dim3(32, 8)>>>(vrr, vtR);
    transpose_v<<<dim3(32, 2, 64), dim3(32, 8)>>>(vff, vtF);

    // Scores: S = (Q K^T) / 8 per (b,h)
    const dim3 gSc(8, 8, BB * HN);
    mma_gemm<false><<<gSc, blk, SMEMSZ>>>(qr, kr, nullptr, sR, nullptr, nullptr,
        DM, DM, SS, DKH, 0.125f,
        (size_t)SS * DM, DKH, (size_t)SS * DM, DKH,
        (size_t)8 * SS * SS, SS * SS);
    mma_gemm<false><<<gSc, blk, SMEMSZ>>>(qf, kf, nullptr, sF, nullptr, nullptr,
        DM, DM, SS, DKH, 0.125f,
        (size_t)SS * DM, DKH, (size_t)SS * DM, DKH,
        (size_t)8 * SS * SS, SS * SS);

    // Dual softmax + max merge (in-place into sR)
    softmax_merge<<<BB * HN * SS, 256>>>(sR, sF, sR);

    // Dual-stream PV: O_r = P @ V_r^T, O_f = P @ V_f^T (one P read)
    mma_gemm<true><<<dim3(1, 8, BB * HN), blk, SMEMSZ>>>(sR, vtR, vtF, orr, off, nullptr,
        SS, SS, DM, SS, 1.f,
        (size_t)8 * SS * SS, SS * SS,
        (size_t)8 * DKH * SS, DKH * SS,
        (size_t)SS * DM, DKH);

    // Output projections into d_out (rgb | flow)
    float* out = (float*)d_out;
    mma_gemm<false><<<gProj, blk, SMEMSZ>>>(orr, Wo1, nullptr, out,      nullptr, bo1,
        DM, DM, DM, DM, 1.f, 0, 0, 0, 0, 0, 0);
    mma_gemm<false><<<gProj, blk, SMEMSZ>>>(off, Wo2, nullptr, out + SL, nullptr, bo2,
        DM, DM, DM, DM, 1.f, 0, 0, 0, 0, 0, 0);
}